// round 13
// baseline (speedup 1.0000x reference)
#include <cuda_runtime.h>
#include <math_constants.h>

// out[c] = dequant(quant(x[c])) with channel c's quant group = inv[c]>>7.
// Block = 4 rows interleaved in smem (s4[c] = {r0..r3}[c], quad-swizzled).
// Warp w gathers permuted group w via prologue-sorted PRE-SWIZZLED indices
// (~conflict-free LDS.128) and reduces min/max for 4 rows. Params go through
// byte-minimal tables: 8x-replicated float4 inv_scale + 32x-replicated packed
// 4-bit bases; scale recovered with rcp.approx (error ~1e-7, final mul only).
// All global traffic is LDG.128/STG.128. 64 KB smem -> 2 CTAs/SM.

#define ROW_C 4096
#define NT    1024
#define RPT   4
#define Q_MAX 15.0f
#define EPS   1e-5f

__device__ int g_sperm[ROW_C];

// float4-element quad swizzle: element i lives in bank-quad swz(i)&7
__device__ __forceinline__ int swz(int i) { return i ^ ((i >> 3) & 7); }

// One warp per group; closed-form dispersal over 8 swizzled-quad bins.
// Element with residue r = swz(p)&7, rank k<16 -> pos k*8+((r-k)&7);
// overflow ranks fill the exact complement holes. Emits swz(p) directly.
// Within-bin order is nondeterministic but min/max cannot observe it.
__global__ void sort_perm_kernel(const int* __restrict__ perm)
{
    __shared__ int emit [32][128];
    __shared__ int holes[32][128];
    __shared__ int cnt[32][8], rk[32][8];
    __shared__ int nhole[32], nov[32];

    const int w    = threadIdx.x >> 5;
    const int lane = threadIdx.x & 31;

    if (lane < 8) { cnt[w][lane] = 0; rk[w][lane] = 0; }
    if (lane == 0) { nhole[w] = 0; nov[w] = 0; }
    __syncwarp();

    int v[4];
    #pragma unroll
    for (int i = 0; i < 4; ++i) {
        v[i] = swz(perm[w * 128 + i * 32 + lane]);       // pre-swizzled
        atomicAdd(&cnt[w][v[i] & 7], 1);
    }
    __syncwarp();

    #pragma unroll
    for (int i = 0; i < 4; ++i) {
        const int p = i * 32 + lane;
        const int c = p >> 3, s = p & 7;
        if (cnt[w][(s + c) & 7] <= c)                    // complement = holes
            holes[w][atomicAdd(&nhole[w], 1)] = p;
    }
    __syncwarp();

    #pragma unroll
    for (int i = 0; i < 4; ++i) {
        const int r = v[i] & 7;
        const int k = atomicAdd(&rk[w][r], 1);
        const int pos = (k < 16) ? (k * 8 + ((r - k) & 7))
                                 : holes[w][atomicAdd(&nov[w], 1)];
        emit[w][pos] = v[i];
    }
    __syncwarp();

    #pragma unroll
    for (int i = 0; i < 4; ++i)
        g_sperm[w * 128 + i * 32 + lane] = emit[w][i * 32 + lane];
}

extern __shared__ float4 smem_dyn[];

__global__ __launch_bounds__(NT, 2)
void tpq_kernel(const float* __restrict__ x,
                const int4*  __restrict__ inv4,
                float*       __restrict__ out)
{
    float4*   s4      = smem_dyn;                      // [4096] float4 = 64 KB
    float4*   tab_inv = s4 + ROW_C;                    // [32*8]  float4 =  4 KB
    unsigned* tab_b   = (unsigned*)(tab_inv + 32 * 8); // [32*32] uint  =  4 KB

    const int t    = threadIdx.x;
    const int warp = t >> 5;
    const int lane = t & 31;
    const int m8   = lane & 7;
    const size_t rowbase = (size_t)blockIdx.x * (RPT * ROW_C);

    int pp[4];                                  // pre-swizzled gather idx
    #pragma unroll
    for (int i = 0; i < 4; ++i)
        pp[i] = g_sperm[warp * 128 + i * 32 + lane];

    // ---- 4 x LDG.128 (rows r0..r3, channels 4t..4t+3); stage swizzled ----
    {
        float4 a0 = __ldcs((const float4*)(x + rowbase)             + t);
        float4 a1 = __ldcs((const float4*)(x + rowbase +     ROW_C) + t);
        float4 a2 = __ldcs((const float4*)(x + rowbase + 2 * ROW_C) + t);
        float4 a3 = __ldcs((const float4*)(x + rowbase + 3 * ROW_C) + t);
        const float* p0 = (const float*)&a0;
        const float* p1 = (const float*)&a1;
        const float* p2 = (const float*)&a2;
        const float* p3 = (const float*)&a3;
        #pragma unroll
        for (int j = 0; j < 4; ++j)
            s4[swz(4 * t + j)] = make_float4(p0[j], p1[j], p2[j], p3[j]);
    }
    __syncthreads();

    // ---- pass A: gather (transient) + reduce min/max for 4 rows ----
    float mn[RPT], mx[RPT];
    #pragma unroll
    for (int r = 0; r < RPT; ++r) { mn[r] = CUDART_INF_F; mx[r] = -CUDART_INF_F; }

    #pragma unroll
    for (int i = 0; i < 4; ++i) {
        const float4 v = s4[pp[i]];             // ~conflict-free LDS.128
        mn[0] = fminf(mn[0], v.x);  mx[0] = fmaxf(mx[0], v.x);
        mn[1] = fminf(mn[1], v.y);  mx[1] = fmaxf(mx[1], v.y);
        mn[2] = fminf(mn[2], v.z);  mx[2] = fmaxf(mx[2], v.z);
        mn[3] = fminf(mn[3], v.w);  mx[3] = fmaxf(mx[3], v.w);
    }
    #pragma unroll
    for (int off = 16; off; off >>= 1) {
        #pragma unroll
        for (int r = 0; r < RPT; ++r) {
            mn[r] = fminf(mn[r], __shfl_xor_sync(0xffffffffu, mn[r], off));
            mx[r] = fmaxf(mx[r], __shfl_xor_sync(0xffffffffu, mx[r], off));
        }
    }

    // ---- tables: exact inv_scale (8x repl) + packed 4-bit bases (32x) ----
    {
        float4 iv;
        float* ivp = (float*)&iv;
        unsigned bu = 0;
        #pragma unroll
        for (int r = 0; r < RPT; ++r) {
            const float scale = fmaxf(mx[r] - mn[r], EPS) / Q_MAX;
            const float inv_s = 1.0f / scale;
            const float base  = fminf(fmaxf(rintf(-mn[r] * inv_s), 0.0f), Q_MAX);
            ivp[r] = inv_s;
            bu |= ((unsigned)base) << (4 * r);
        }
        if (lane < 8) tab_inv[warp * 8 + lane] = iv;
        tab_b[warp * 32 + lane] = bu;           // conflict-free (bank=lane)
    }

    const int4 gi = __ldg(&inv4[t]);            // groups of channels 4t..4t+3
    int g[4] = { gi.x >> 7, gi.y >> 7, gi.z >> 7, gi.w >> 7 };
    __syncthreads();

    // ---- pass B: reread staged values, quantize, 4 x STG.128 ----
    float4 o0, o1, o2, o3;
    float* q0 = (float*)&o0;
    float* q1 = (float*)&o1;
    float* q2 = (float*)&o2;
    float* q3 = (float*)&o3;
    #pragma unroll
    for (int j = 0; j < 4; ++j) {
        const float4   d  = s4[swz(4 * t + j)];        // 4 rows of channel
        const float4   iv = tab_inv[g[j] * 8 + m8];    // conflict-free
        const unsigned bu = tab_b [g[j] * 32 + lane];  // conflict-free
        const float* dp  = (const float*)&d;
        const float* ivp = (const float*)&iv;
        float r_[4];
        #pragma unroll
        for (int r = 0; r < RPT; ++r) {
            float sc;                                  // scale = rcp(inv_scale)
            asm("rcp.approx.f32 %0, %1;" : "=f"(sc) : "f"(ivp[r]));
            const float b = (float)((bu >> (4 * r)) & 15u);
            float q = rintf(dp[r] * ivp[r]);
            q = fminf(fmaxf(q, -b), Q_MAX - b);        // == clip(q+b,0,15)-b
            r_[r] = q * sc;
        }
        q0[j] = r_[0];  q1[j] = r_[1];  q2[j] = r_[2];  q3[j] = r_[3];
    }
    __stcg((float4*)(out + rowbase)             + t, o0);
    __stcg((float4*)(out + rowbase +     ROW_C) + t, o1);
    __stcg((float4*)(out + rowbase + 2 * ROW_C) + t, o2);
    __stcg((float4*)(out + rowbase + 3 * ROW_C) + t, o3);
}

extern "C" void kernel_launch(void* const* d_in, const int* in_sizes, int n_in,
                              void* d_out, int out_size)
{
    const float* x    = (const float*)d_in[0];
    const int*   perm = (const int*)d_in[1];
    const int4*  inv4 = (const int4*)d_in[2];
    float*       out  = (float*)d_out;

    sort_perm_kernel<<<1, NT>>>(perm);

    const int smem_bytes = ROW_C * sizeof(float4)
                         + 32 * 8 * sizeof(float4)
                         + 32 * 32 * sizeof(unsigned);
    cudaFuncSetAttribute(tpq_kernel,
                         cudaFuncAttributeMaxDynamicSharedMemorySize, smem_bytes);

    const int rows = in_sizes[0] / ROW_C;              // 16384
    tpq_kernel<<<rows / RPT, NT, smem_bytes>>>(x, inv4, out);
}